// round 15
// baseline (speedup 1.0000x reference)
#include <cuda_runtime.h>
#include <cstdint>
#include <math.h>

#define V 30522
#define NBATCH 2
#define SLEN 512
#define DIM 768
#define NJ 12
#define NBK 4
#define NUM_LABELS 7
#define M_TOK (NBATCH*SLEN)   /* 1024 */
#define KDIM (13*DIM)         /* 9984 */
#define GDIM (NJ*DIM)         /* 9216 */
#define NPAIR (NJ*13)         /* 156 */
#define SMALL_MAX 32

#define ROWP 36
#define STAGE_F ((64+128)*ROWP)           /* big path stage: 6912 floats (27648 B) */
#define STAGE_S_F ((32+128)*ROWP)         /* small path stage: 5760 floats (23040 B) */
#define SMEM_U_BYTES (4*STAGE_F*4)        /* 110592: 4-stage big path; small path uses 3x23040 */
#define SMEM_AO_BYTES (3*STAGE_F*4)       /* 82944: attnout 3-stage (as in R10) */

// ---------------- scratch ----------------
__device__ int   g_lp0[V];
__device__ int   g_lp1[V];
__device__ float g_nflat[(size_t)M_TOK*GDIM];
__device__ float g_pre[(size_t)M_TOK*GDIM];
__device__ float g_combined[(size_t)M_TOK*2*DIM];
__device__ unsigned int g_amask[M_TOK];
__device__ int   g_pcount[NPAIR];
__device__ int   g_plist[NPAIR*M_TOK];

// ---------------- helpers ----------------
__device__ __forceinline__ uint32_t smem_u32(const void* p) {
    uint32_t a; asm("{ .reg .u64 t; cvta.to.shared.u64 t, %1; cvt.u32.u64 %0, t; }" : "=r"(a) : "l"(p));
    return a;
}
__device__ __forceinline__ void cp16(uint32_t saddr, const void* g) {
    asm volatile("cp.async.ca.shared.global [%0], [%1], 16;" :: "r"(saddr), "l"(g));
}
#define CP_COMMIT() asm volatile("cp.async.commit_group;" ::: "memory")
#define CP_WAIT2()  asm volatile("cp.async.wait_group 2;" ::: "memory")

__device__ __forceinline__ void mma_tf32(float* c, const uint32_t* a, const uint32_t* b) {
    asm volatile("mma.sync.aligned.m16n8k8.row.col.f32.tf32.tf32.f32 "
                 "{%0,%1,%2,%3}, {%4,%5,%6,%7}, {%8,%9}, {%0,%1,%2,%3};"
                 : "+f"(c[0]), "+f"(c[1]), "+f"(c[2]), "+f"(c[3])
                 : "r"(a[0]), "r"(a[1]), "r"(a[2]), "r"(a[3]), "r"(b[0]), "r"(b[1]));
}

// ---------------- small kernels ----------------
__global__ void k_init() {
    int i = blockIdx.x*blockDim.x + threadIdx.x;
    if (i < V) { g_lp0[i] = -1; g_lp1[i] = -1; }
    if (i < M_TOK) g_amask[i] = 0;
}
__global__ void k_scatter2(const int* __restrict__ ids) {
    int* lp = blockIdx.x ? g_lp1 : g_lp0;
    atomicMax(&lp[ids[blockIdx.x*SLEN + threadIdx.x]], (int)threadIdx.x);
}

__global__ void k_emb_all(const int* __restrict__ nb, const float* __restrict__ seq,
                          const float* __restrict__ bmlp) {
    int blk = blockIdx.x;             // (b*512+s)*12 + j
    int j = blk % NJ;
    int m = blk / NJ;
    int b = m >> 9;
    const int* nbp = nb + (size_t)blk * NBK;
    int src[4];
    #pragma unroll
    for (int i = 0; i < 4; i++) {
        int id = nbp[i];
        int s0 = g_lp0[id];
        if (b) { int s1 = g_lp1[id]; src[i] = (s1 >= 0) ? (SLEN + s1) : s0; }
        else src[i] = s0;
    }
    if (src[0] < 0 && src[1] < 0 && src[2] < 0 && src[3] < 0) return;
    int t = threadIdx.x;              // 192 threads * float4 = 768
    float4 acc = make_float4(0.f,0.f,0.f,0.f);
    #pragma unroll
    for (int i = 0; i < 4; i++) {
        if (src[i] >= 0) {
            float4 v = ((const float4*)(seq + (size_t)src[i]*DIM))[t];
            acc.x += v.x; acc.y += v.y; acc.z += v.z; acc.w += v.w;
        }
    }
    ((float4*)(g_nflat + (size_t)m*GDIM + (size_t)j*DIM))[t] = acc;
    float4 bv = ((const float4*)(bmlp + (size_t)j*DIM))[t];
    ((float4*)(g_pre + (size_t)m*GDIM + (size_t)j*DIM))[t] = bv;
    if (t == 0) atomicOr(&g_amask[m], 1u << j);
}

// 156 blocks; ballot compaction, no atomics.
__global__ __launch_bounds__(256) void k_pairs2() {
    int pid = blockIdx.x;
    int j = pid / 13, c = pid % 13;
    int tid = threadIdx.x, lane = tid & 31, wid = tid >> 5;
    __shared__ int wcnt[8];
    int total = 0;
    for (int m0 = 0; m0 < M_TOK; m0 += 256) {
        int m = m0 + tid;
        unsigned mask = g_amask[m];
        bool ok = ((mask >> j) & 1u) && (c == 0 || ((mask >> (c-1)) & 1u));
        unsigned bal = __ballot_sync(0xffffffffu, ok);
        if (lane == 0) wcnt[wid] = __popc(bal);
        __syncthreads();
        int woff = 0, bsum = 0;
        #pragma unroll
        for (int i = 0; i < 8; i++) { if (i < wid) woff += wcnt[i]; bsum += wcnt[i]; }
        if (ok) {
            int pos = total + woff + __popc(bal & ((1u << lane) - 1u));
            g_plist[pid*M_TOK + pos] = m;
        }
        total += bsum;
        __syncthreads();
    }
    if (tid == 0) g_pcount[pid] = total;
}

// ============ 64x128 mma stage (warps 2m x 4n, frags 2m x 4n) ============
__device__ __forceinline__ void mma_stage64(const uint32_t* sbase, int wm, int wn,
                                            int gid, int tig, float acc[2][4][4]) {
    const uint32_t* As = sbase;
    const uint32_t* Bs = sbase + 64*ROWP;
    #pragma unroll
    for (int ks = 0; ks < 4; ks++) {
        uint32_t a[2][4], b[4][2];
        #pragma unroll
        for (int mt = 0; mt < 2; mt++) {
            int r0 = wm*32 + mt*16 + gid;
            a[mt][0] = As[r0*ROWP + ks*8 + tig];
            a[mt][1] = As[(r0+8)*ROWP + ks*8 + tig];
            a[mt][2] = As[r0*ROWP + ks*8 + tig + 4];
            a[mt][3] = As[(r0+8)*ROWP + ks*8 + tig + 4];
        }
        #pragma unroll
        for (int nt = 0; nt < 4; nt++) {
            int n = wn*32 + nt*8 + gid;
            b[nt][0] = Bs[n*ROWP + ks*8 + tig];
            b[nt][1] = Bs[n*ROWP + ks*8 + tig + 4];
        }
        #pragma unroll
        for (int mt = 0; mt < 2; mt++)
            #pragma unroll
            for (int nt = 0; nt < 4; nt++)
                mma_tf32(acc[mt][nt], a[mt], b[nt]);
    }
}

// ============ 32x128 mma stage ============
__device__ __forceinline__ void mma_stage32(const uint32_t* sbase, int wm, int wn,
                                            int gid, int tig, float acc[4][4]) {
    const uint32_t* As = sbase;
    const uint32_t* Bs = sbase + 32*ROWP;
    #pragma unroll
    for (int ks = 0; ks < 4; ks++) {
        uint32_t a[4], b[4][2];
        int r0 = wm*16 + gid;
        a[0] = As[r0*ROWP + ks*8 + tig];
        a[1] = As[(r0+8)*ROWP + ks*8 + tig];
        a[2] = As[r0*ROWP + ks*8 + tig + 4];
        a[3] = As[(r0+8)*ROWP + ks*8 + tig + 4];
        #pragma unroll
        for (int nt = 0; nt < 4; nt++) {
            int n = wn*32 + nt*8 + gid;
            b[nt][0] = Bs[n*ROWP + ks*8 + tig];
            b[nt][1] = Bs[n*ROWP + ks*8 + tig + 4];
        }
        #pragma unroll
        for (int nt = 0; nt < 4; nt++)
            mma_tf32(acc[nt], a, b[nt]);
    }
}

// ---------------- unified sparse GEMM (grid 3x6x156; big path 64x128 4-stage, .ca) ----------------
__global__ __launch_bounds__(256) void k_gemmU2(const float* __restrict__ seq,
                                                const float* __restrict__ Wmlp) {
    int pid = blockIdx.z;
    int jout = pid / 13, chunk = pid % 13;
    int cnt = g_pcount[pid];
    if (cnt == 0) return;
    const int* list = g_plist + pid*M_TOK;
    const float* abase = chunk ? (g_nflat + (size_t)(chunk-1)*768) : seq;
    size_t astride = chunk ? (size_t)GDIM : (size_t)DIM;
    int nbase = blockIdx.y * 128;
    size_t boff = (size_t)chunk*768;

    extern __shared__ float smem[];
    __shared__ int rows_sh[64];
    uint32_t sb = smem_u32(smem);
    int tid = threadIdx.x;
    int wid = tid >> 5, lane = tid & 31;
    int gid = lane >> 2, tig = lane & 3;
    const int NS = 24;

    if (cnt <= SMALL_MAX) {
        // ---- 32x128 path, 3-stage: CTAs (x==0) ----
        if (blockIdx.x != 0) return;
        int wm = wid & 1, wn = wid >> 1;

        if (tid < 32) rows_sh[tid] = (tid < cnt) ? list[tid] : -1;
        __syncthreads();

        int arow_l = tid >> 3, aseg0 = tid & 7;
        int arow = rows_sh[arow_l];
        const float* aptr = abase + (size_t)(arow < 0 ? 0 : arow)*astride + aseg0*4;
        uint32_t sa = sb + (arow_l*ROWP + aseg0*4)*4;
        const float* bptr[4];
        uint32_t sbb[4];
        #pragma unroll
        for (int i = 0; i < 4; i++) {
            int idx = i*256 + tid;
            int row = idx >> 3, seg = idx & 7;
            bptr[i] = Wmlp + (size_t)(jout*768 + nbase + row)*KDIM + boff + seg*4;
            sbb[i] = sb + ((32*ROWP) + row*ROWP + seg*4)*4;
        }

        #pragma unroll
        for (int s = 0; s < 3; s++) {
            uint32_t so = s*STAGE_S_F*4;
            cp16(sa + so, aptr + s*32);
            #pragma unroll
            for (int i = 0; i < 4; i++) cp16(sbb[i] + so, bptr[i] + s*32);
            CP_COMMIT();
        }

        float acc[4][4];
        #pragma unroll
        for (int nt = 0; nt < 4; nt++)
            #pragma unroll
            for (int q = 0; q < 4; q++) acc[nt][q] = 0.f;

        for (int s = 0; s < NS; s++) {
            CP_WAIT2();
            __syncthreads();
            int slot = s % 3;
            mma_stage32((const uint32_t*)smem + slot*STAGE_S_F, wm, wn, gid, tig, acc);
            __syncthreads();
            if (s + 3 < NS) {
                uint32_t so = slot*STAGE_S_F*4;
                cp16(sa + so, aptr + (s + 3)*32);
                #pragma unroll
                for (int i = 0; i < 4; i++) cp16(sbb[i] + so, bptr[i] + (s + 3)*32);
            }
            CP_COMMIT();
        }

        #pragma unroll
        for (int half = 0; half < 2; half++) {
            int lr = wm*16 + gid + half*8;
            int row = rows_sh[lr];
            if (row < 0) continue;
            float* dst = g_pre + (size_t)row*GDIM + jout*768 + nbase;
            #pragma unroll
            for (int nt = 0; nt < 4; nt++) {
                int n = wn*32 + nt*8 + 2*tig;
                atomicAdd(&dst[n],   acc[nt][half*2 + 0]);
                atomicAdd(&dst[n+1], acc[nt][half*2 + 1]);
            }
        }
    } else {
        // ---- 64x128 path, 4-stage (3 stages of loads in flight), all .ca ----
        int wm = wid & 1, wn = wid >> 1;

        const float* bptr[4];
        uint32_t sbb[4];
        #pragma unroll
        for (int i = 0; i < 4; i++) {
            int idx = i*256 + tid;
            int row = idx >> 3, seg = idx & 7;
            bptr[i] = Wmlp + (size_t)(jout*768 + nbase + row)*KDIM + boff + seg*4;
            sbb[i] = sb + ((64*ROWP) + row*ROWP + seg*4)*4;
        }
        int arow_l[2]; int aseg[2]; uint32_t sa[2];
        #pragma unroll
        for (int i = 0; i < 2; i++) {
            int idx = i*256 + tid;
            arow_l[i] = idx >> 3; aseg[i] = idx & 7;
            sa[i] = sb + (arow_l[i]*ROWP + aseg[i]*4)*4;
        }

        for (int mt0 = blockIdx.x; mt0*64 < cnt; mt0 += gridDim.x) {
            int m0 = mt0*64;
            __syncthreads();
            if (tid < 64) {
                int mi = m0 + tid;
                rows_sh[tid] = (mi < cnt) ? list[mi] : -1;
            }
            __syncthreads();

            const float* aptr[2];
            #pragma unroll
            for (int i = 0; i < 2; i++) {
                int arow = rows_sh[arow_l[i]];
                aptr[i] = abase + (size_t)(arow < 0 ? 0 : arow)*astride + aseg[i]*4;
            }

            // prologue: fill 3 of 4 slots
            #pragma unroll
            for (int s = 0; s < 3; s++) {
                uint32_t so = s*STAGE_F*4;
                #pragma unroll
                for (int i = 0; i < 2; i++) cp16(sa[i] + so, aptr[i] + s*32);
                #pragma unroll
                for (int i = 0; i < 4; i++) cp16(sbb[i] + so, bptr[i] + s*32);
                CP_COMMIT();
            }

            float acc[2][4][4];
            #pragma unroll
            for (int mt = 0; mt < 2; mt++)
                #pragma unroll
                for (int nt = 0; nt < 4; nt++)
                    #pragma unroll
                    for (int q = 0; q < 4; q++) acc[mt][nt][q] = 0.f;

            for (int s = 0; s < NS; s++) {
                CP_WAIT2();
                __syncthreads();
                int slot = s & 3;
                mma_stage64((const uint32_t*)smem + slot*STAGE_F, wm, wn, gid, tig, acc);
                __syncthreads();
                if (s + 3 < NS) {
                    uint32_t so = ((s + 3) & 3)*STAGE_F*4;
                    #pragma unroll
                    for (int i = 0; i < 2; i++) cp16(sa[i] + so, aptr[i] + (s + 3)*32);
                    #pragma unroll
                    for (int i = 0; i < 4; i++) cp16(sbb[i] + so, bptr[i] + (s + 3)*32);
                }
                CP_COMMIT();
            }

            #pragma unroll
            for (int mt = 0; mt < 2; mt++) {
                #pragma unroll
                for (int half = 0; half < 2; half++) {
                    int lr = wm*32 + mt*16 + gid + half*8;
                    int row = rows_sh[lr];
                    if (row < 0) continue;
                    float* dst = g_pre + (size_t)row*GDIM + jout*768 + nbase;
                    #pragma unroll
                    for (int nt = 0; nt < 4; nt++) {
                        int n = wn*32 + nt*8 + 2*tig;
                        atomicAdd(&dst[n],   acc[mt][nt][half*2 + 0]);
                        atomicAdd(&dst[n+1], acc[mt][nt][half*2 + 1]);
                    }
                }
            }
        }
    }
}

// ---------------- fused gate + attention + logits seq-part ----------------
__global__ __launch_bounds__(256) void k_attn2(const float* __restrict__ seq,
                                               const float* __restrict__ Wcls,
                                               const float* __restrict__ bcls,
                                               float* __restrict__ out) {
    extern __shared__ float sm[];
    float* sseq = sm;
    float* cbuf = sm + DIM;
    __shared__ float sc[NJ], swt[NJ];
    int m = blockIdx.x, t = threadIdx.x;
    int wid = t >> 5, lane = t & 31;
    unsigned mask = g_amask[m];
    for (int d = t; d < DIM; d += 256) sseq[d] = seq[(size_t)m*DIM + d];
    if (t < NJ) sc[t] = 0.f;
    __syncthreads();

    for (int j = wid; j < NJ; j += 8) {
        if (mask & (1u << j)) {
            const float* pre = g_pre + (size_t)m*GDIM + j*768;
            const float* nf  = g_nflat + (size_t)m*GDIM + j*768;
            float part = 0.f;
            for (int d = lane; d < DIM; d += 32) {
                float cv = (1.f / (1.f + expf(-pre[d]))) * nf[d];
                cbuf[j*768 + d] = cv;
                part += cv * sseq[d];
            }
            #pragma unroll
            for (int o = 16; o; o >>= 1) part += __shfl_xor_sync(0xffffffffu, part, o);
            if (lane == 0) sc[j] = part;
        }
    }
    __syncthreads();
    if (t == 0) {
        float mx = sc[0];
        #pragma unroll
        for (int j = 1; j < NJ; j++) mx = fmaxf(mx, sc[j]);
        float sum = 0.f;
        #pragma unroll
        for (int j = 0; j < NJ; j++) { float e = expf(sc[j]-mx); swt[j] = e; sum += e; }
        float inv = 1.f/sum;
        #pragma unroll
        for (int j = 0; j < NJ; j++) swt[j] *= inv;
    }
    __syncthreads();
    for (int d = t; d < DIM; d += 256) {
        float mix = 0.f;
        unsigned m2 = mask;
        while (m2) {
            int j = __ffs(m2) - 1; m2 &= m2 - 1;
            mix += swt[j] * cbuf[j*768 + d];
        }
        g_combined[(size_t)m*2*DIM + d]       = mix;
        g_combined[(size_t)m*2*DIM + DIM + d] = sseq[d];
    }
    if (wid < NUM_LABELS) {
        const float* wr = Wcls + (size_t)wid*2*DIM;
        float p = 0.f;
        for (int d = lane; d < DIM; d += 32) p += sseq[d]*wr[d];
        #pragma unroll
        for (int o = 16; o; o >>= 1) p += __shfl_xor_sync(0xffffffffu, p, o);
        if (lane == 0) out[m*NUM_LABELS + wid] = p + bcls[wid];
    }
}

// ---------------- attn_out GEMM + fused logits tanh-part (64x128, 3-stage, as R10) ----------------
__global__ __launch_bounds__(256) void k_attnout_mma(const float* __restrict__ Wattn,
                                                     const float* __restrict__ battn,
                                                     const float* __restrict__ Wcls,
                                                     float* __restrict__ out) {
    const int KD = 2*DIM;
    int m0 = blockIdx.x * 64;
    int nbase = blockIdx.y * 128;

    extern __shared__ float smem[];
    __shared__ float sWcls[NUM_LABELS][128];
    uint32_t sb = smem_u32(smem);
    int tid = threadIdx.x;
    int wid = tid >> 5, lane = tid & 31;
    int gid = lane >> 2, tig = lane & 3;
    int wm = wid & 1, wn = wid >> 1;

    for (int idx = tid; idx < NUM_LABELS*128; idx += 256) {
        int l = idx >> 7, c = idx & 127;
        sWcls[l][c] = Wcls[(size_t)l*KD + DIM + nbase + c];
    }

    const float* bptr[4];
    uint32_t sbb[4];
    #pragma unroll
    for (int i = 0; i < 4; i++) {
        int idx = i*256 + tid;
        int row = idx >> 3, seg = idx & 7;
        bptr[i] = Wattn + (size_t)(nbase + row)*KD + seg*4;
        sbb[i] = sb + ((64*ROWP) + row*ROWP + seg*4)*4;
    }
    const float* aptr[2];
    uint32_t sa[2];
    #pragma unroll
    for (int i = 0; i < 2; i++) {
        int idx = i*256 + tid;
        int row = idx >> 3, seg = idx & 7;
        aptr[i] = g_combined + (size_t)(m0 + row)*KD + seg*4;
        sa[i] = sb + (row*ROWP + seg*4)*4;
    }

    const int NS = 48;
    #pragma unroll
    for (int s = 0; s < 3; s++) {
        uint32_t so = s*STAGE_F*4;
        #pragma unroll
        for (int i = 0; i < 2; i++) cp16(sa[i] + so, aptr[i] + s*32);
        #pragma unroll
        for (int i = 0; i < 4; i++) cp16(sbb[i] + so, bptr[i] + s*32);
        CP_COMMIT();
    }

    float acc[2][4][4];
    #pragma unroll
    for (int mt = 0; mt < 2; mt++)
        #pragma unroll
        for (int nt = 0; nt < 4; nt++)
            #pragma unroll
            for (int q = 0; q < 4; q++) acc[mt][nt][q] = 0.f;

    for (int s = 0; s < NS; s++) {
        CP_WAIT2();
        __syncthreads();
        int slot = s % 3;
        mma_stage64((const uint32_t*)smem + slot*STAGE_F, wm, wn, gid, tig, acc);
        __syncthreads();
        if (s + 3 < NS) {
            uint32_t so = slot*STAGE_F*4;
            #pragma unroll
            for (int i = 0; i < 2; i++) cp16(sa[i] + so, aptr[i] + (s + 3)*32);
            #pragma unroll
            for (int i = 0; i < 4; i++) cp16(sbb[i] + so, bptr[i] + (s + 3)*32);
        }
        CP_COMMIT();
    }

    #pragma unroll
    for (int mt = 0; mt < 2; mt++) {
        #pragma unroll
        for (int half = 0; half < 2; half++) {
            int m = m0 + wm*32 + mt*16 + gid + half*8;
            float lg[NUM_LABELS];
            #pragma unroll
            for (int l = 0; l < NUM_LABELS; l++) lg[l] = 0.f;
            #pragma unroll
            for (int nt = 0; nt < 4; nt++) {
                int c = wn*32 + nt*8 + 2*tig;
                int n = nbase + c;
                float v0 = tanhf(acc[mt][nt][half*2 + 0] + battn[n]);
                float v1 = tanhf(acc[mt][nt][half*2 + 1] + battn[n+1]);
                #pragma unroll
                for (int l = 0; l < NUM_LABELS; l++)
                    lg[l] += v0*sWcls[l][c] + v1*sWcls[l][c+1];
            }
            #pragma unroll
            for (int l = 0; l < NUM_LABELS; l++)
                atomicAdd(&out[m*NUM_LABELS + l], lg[l]);
        }
    }
}

// ---------------- launch ----------------
extern "C" void kernel_launch(void* const* d_in, const int* in_sizes, int n_in,
                              void* d_out, int out_size) {
    const float* seq   = (const float*)d_in[0];
    const int*   ids   = (const int*)  d_in[1];
    const int*   nb    = (const int*)  d_in[2];
    const float* Wmlp  = (const float*)d_in[3];
    const float* bmlp  = (const float*)d_in[4];
    const float* Wattn = (const float*)d_in[5];
    const float* battn = (const float*)d_in[6];
    const float* Wcls  = (const float*)d_in[7];
    const float* bcls  = (const float*)d_in[8];
    float* out = (float*)d_out;

    cudaFuncSetAttribute(k_gemmU2,      cudaFuncAttributeMaxDynamicSharedMemorySize, SMEM_U_BYTES);
    cudaFuncSetAttribute(k_attnout_mma, cudaFuncAttributeMaxDynamicSharedMemorySize, SMEM_AO_BYTES);

    k_init<<<(V+255)/256, 256>>>();
    k_scatter2<<<2, SLEN>>>(ids);
    k_emb_all<<<M_TOK*NJ, 192>>>(nb, seq, bmlp);
    k_pairs2<<<NPAIR, 256>>>();
    dim3 gu(3, 6, NPAIR);
    k_gemmU2<<<gu, 256, SMEM_U_BYTES>>>(seq, Wmlp);
    int attn_smem = (DIM + NJ*DIM)*4;
    k_attn2<<<M_TOK, 256, attn_smem>>>(seq, Wcls, bcls, out);
    dim3 go(M_TOK/64, 6);
    k_attnout_mma<<<go, 256, SMEM_AO_BYTES>>>(Wattn, battn, Wcls, out);
}

// round 16
// speedup vs baseline: 1.1303x; 1.1303x over previous
#include <cuda_runtime.h>
#include <cstdint>
#include <math.h>

#define V 30522
#define NBATCH 2
#define SLEN 512
#define DIM 768
#define NJ 12
#define NBK 4
#define NUM_LABELS 7
#define M_TOK (NBATCH*SLEN)   /* 1024 */
#define KDIM (13*DIM)         /* 9984 */
#define GDIM (NJ*DIM)         /* 9216 */
#define NPAIR (NJ*13)         /* 156 */
#define SMALL_MAX 32

#define ROWP 36
#define STAGE_F ((64+128)*ROWP)           /* big path stage: 6912 floats */
#define STAGE_S_F ((32+128)*ROWP)         /* small path stage: 5760 floats */
#define SMEM_U_BYTES (3*STAGE_F*4)        /* 82944 */

// ---------------- scratch (zero-initialized; lastpos uses pos+1, 0 = absent) ----------------
__device__ int   g_lp0[V];
__device__ int   g_lp1[V];
__device__ float g_nflat[(size_t)M_TOK*GDIM];
__device__ float g_pre[(size_t)M_TOK*GDIM];
__device__ float g_combined[(size_t)M_TOK*2*DIM];
__device__ unsigned int g_amask[M_TOK];
__device__ int   g_pcount[NPAIR];
__device__ int   g_plist[NPAIR*M_TOK];

// ---------------- helpers ----------------
__device__ __forceinline__ uint32_t smem_u32(const void* p) {
    uint32_t a; asm("{ .reg .u64 t; cvta.to.shared.u64 t, %1; cvt.u32.u64 %0, t; }" : "=r"(a) : "l"(p));
    return a;
}
__device__ __forceinline__ void cp16(uint32_t saddr, const void* g) {
    asm volatile("cp.async.ca.shared.global [%0], [%1], 16;" :: "r"(saddr), "l"(g));
}
#define CP_COMMIT() asm volatile("cp.async.commit_group;" ::: "memory")
#define CP_WAIT2()  asm volatile("cp.async.wait_group 2;" ::: "memory")

__device__ __forceinline__ void mma_tf32(float* c, const uint32_t* a, const uint32_t* b) {
    asm volatile("mma.sync.aligned.m16n8k8.row.col.f32.tf32.tf32.f32 "
                 "{%0,%1,%2,%3}, {%4,%5,%6,%7}, {%8,%9}, {%0,%1,%2,%3};"
                 : "+f"(c[0]), "+f"(c[1]), "+f"(c[2]), "+f"(c[3])
                 : "r"(a[0]), "r"(a[1]), "r"(a[2]), "r"(a[3]), "r"(b[0]), "r"(b[1]));
}

// ---------------- small kernels ----------------
// lastpos encoded as pos+1 (0 = absent) -> zero-init is the valid empty state.
__global__ void k_scatter2(const int* __restrict__ ids) {
    int* lp = blockIdx.x ? g_lp1 : g_lp0;
    atomicMax(&lp[ids[blockIdx.x*SLEN + threadIdx.x]], (int)threadIdx.x + 1);
}

__global__ void k_emb_all(const int* __restrict__ nb, const float* __restrict__ seq,
                          const float* __restrict__ bmlp) {
    int blk = blockIdx.x;             // (b*512+s)*12 + j
    int j = blk % NJ;
    int m = blk / NJ;
    int b = m >> 9;
    const int* nbp = nb + (size_t)blk * NBK;
    int src[4];
    #pragma unroll
    for (int i = 0; i < 4; i++) {
        int id = nbp[i];
        int p0 = g_lp0[id];
        if (b) { int p1 = g_lp1[id]; src[i] = p1 ? (SLEN + p1 - 1) : (p0 - 1); }
        else src[i] = p0 - 1;
    }
    if (src[0] < 0 && src[1] < 0 && src[2] < 0 && src[3] < 0) return;
    int t = threadIdx.x;              // 192 threads * float4 = 768
    float4 acc = make_float4(0.f,0.f,0.f,0.f);
    #pragma unroll
    for (int i = 0; i < 4; i++) {
        if (src[i] >= 0) {
            float4 v = ((const float4*)(seq + (size_t)src[i]*DIM))[t];
            acc.x += v.x; acc.y += v.y; acc.z += v.z; acc.w += v.w;
        }
    }
    ((float4*)(g_nflat + (size_t)m*GDIM + (size_t)j*DIM))[t] = acc;
    float4 bv = ((const float4*)(bmlp + (size_t)j*DIM))[t];
    ((float4*)(g_pre + (size_t)m*GDIM + (size_t)j*DIM))[t] = bv;
    if (t == 0) atomicOr(&g_amask[m], 1u << j);
}

// 156 blocks; ballot compaction, no atomics.
__global__ __launch_bounds__(256) void k_pairs2() {
    int pid = blockIdx.x;
    int j = pid / 13, c = pid % 13;
    int tid = threadIdx.x, lane = tid & 31, wid = tid >> 5;
    __shared__ int wcnt[8];
    int total = 0;
    for (int m0 = 0; m0 < M_TOK; m0 += 256) {
        int m = m0 + tid;
        unsigned mask = g_amask[m];
        bool ok = ((mask >> j) & 1u) && (c == 0 || ((mask >> (c-1)) & 1u));
        unsigned bal = __ballot_sync(0xffffffffu, ok);
        if (lane == 0) wcnt[wid] = __popc(bal);
        __syncthreads();
        int woff = 0, bsum = 0;
        #pragma unroll
        for (int i = 0; i < 8; i++) { if (i < wid) woff += wcnt[i]; bsum += wcnt[i]; }
        if (ok) {
            int pos = total + woff + __popc(bal & ((1u << lane) - 1u));
            g_plist[pid*M_TOK + pos] = m;
        }
        total += bsum;
        __syncthreads();
    }
    if (tid == 0) g_pcount[pid] = total;
}

// ============ 64x128 mma stage (warps 2m x 4n, frags 2m x 4n) ============
__device__ __forceinline__ void mma_stage64(const uint32_t* sbase, int wm, int wn,
                                            int gid, int tig, float acc[2][4][4]) {
    const uint32_t* As = sbase;
    const uint32_t* Bs = sbase + 64*ROWP;
    #pragma unroll
    for (int ks = 0; ks < 4; ks++) {
        uint32_t a[2][4], b[4][2];
        #pragma unroll
        for (int mt = 0; mt < 2; mt++) {
            int r0 = wm*32 + mt*16 + gid;
            a[mt][0] = As[r0*ROWP + ks*8 + tig];
            a[mt][1] = As[(r0+8)*ROWP + ks*8 + tig];
            a[mt][2] = As[r0*ROWP + ks*8 + tig + 4];
            a[mt][3] = As[(r0+8)*ROWP + ks*8 + tig + 4];
        }
        #pragma unroll
        for (int nt = 0; nt < 4; nt++) {
            int n = wn*32 + nt*8 + gid;
            b[nt][0] = Bs[n*ROWP + ks*8 + tig];
            b[nt][1] = Bs[n*ROWP + ks*8 + tig + 4];
        }
        #pragma unroll
        for (int mt = 0; mt < 2; mt++)
            #pragma unroll
            for (int nt = 0; nt < 4; nt++)
                mma_tf32(acc[mt][nt], a[mt], b[nt]);
    }
}

// ============ 32x128 mma stage ============
__device__ __forceinline__ void mma_stage32(const uint32_t* sbase, int wm, int wn,
                                            int gid, int tig, float acc[4][4]) {
    const uint32_t* As = sbase;
    const uint32_t* Bs = sbase + 32*ROWP;
    #pragma unroll
    for (int ks = 0; ks < 4; ks++) {
        uint32_t a[4], b[4][2];
        int r0 = wm*16 + gid;
        a[0] = As[r0*ROWP + ks*8 + tig];
        a[1] = As[(r0+8)*ROWP + ks*8 + tig];
        a[2] = As[r0*ROWP + ks*8 + tig + 4];
        a[3] = As[(r0+8)*ROWP + ks*8 + tig + 4];
        #pragma unroll
        for (int nt = 0; nt < 4; nt++) {
            int n = wn*32 + nt*8 + gid;
            b[nt][0] = Bs[n*ROWP + ks*8 + tig];
            b[nt][1] = Bs[n*ROWP + ks*8 + tig + 4];
        }
        #pragma unroll
        for (int nt = 0; nt < 4; nt++)
            mma_tf32(acc[nt], a, b[nt]);
    }
}

// ---------------- unified size-adaptive sparse GEMM (grid 3x6x156; R10 config) ----------------
__global__ __launch_bounds__(256) void k_gemmU2(const float* __restrict__ seq,
                                                const float* __restrict__ Wmlp) {
    int pid = blockIdx.z;
    int jout = pid / 13, chunk = pid % 13;
    int cnt = g_pcount[pid];
    if (cnt == 0) return;
    const int* list = g_plist + pid*M_TOK;
    const float* abase = chunk ? (g_nflat + (size_t)(chunk-1)*768) : seq;
    size_t astride = chunk ? (size_t)GDIM : (size_t)DIM;
    int nbase = blockIdx.y * 128;
    size_t boff = (size_t)chunk*768;

    extern __shared__ float smem[];
    __shared__ int rows_sh[64];
    uint32_t sb = smem_u32(smem);
    int tid = threadIdx.x;
    int wid = tid >> 5, lane = tid & 31;
    int gid = lane >> 2, tig = lane & 3;
    const int NS = 24;

    if (cnt <= SMALL_MAX) {
        // ---- 32x128 path, 3-stage: CTAs (x==0) ----
        if (blockIdx.x != 0) return;
        int wm = wid & 1, wn = wid >> 1;

        if (tid < 32) rows_sh[tid] = (tid < cnt) ? list[tid] : -1;
        __syncthreads();

        int arow_l = tid >> 3, aseg0 = tid & 7;
        int arow = rows_sh[arow_l];
        const float* aptr = abase + (size_t)(arow < 0 ? 0 : arow)*astride + aseg0*4;
        uint32_t sa = sb + (arow_l*ROWP + aseg0*4)*4;
        const float* bptr[4];
        uint32_t sbb[4];
        #pragma unroll
        for (int i = 0; i < 4; i++) {
            int idx = i*256 + tid;
            int row = idx >> 3, seg = idx & 7;
            bptr[i] = Wmlp + (size_t)(jout*768 + nbase + row)*KDIM + boff + seg*4;
            sbb[i] = sb + ((32*ROWP) + row*ROWP + seg*4)*4;
        }

        #pragma unroll
        for (int s = 0; s < 3; s++) {
            uint32_t so = s*STAGE_S_F*4;
            cp16(sa + so, aptr + s*32);
            #pragma unroll
            for (int i = 0; i < 4; i++) cp16(sbb[i] + so, bptr[i] + s*32);
            CP_COMMIT();
        }

        float acc[4][4];
        #pragma unroll
        for (int nt = 0; nt < 4; nt++)
            #pragma unroll
            for (int q = 0; q < 4; q++) acc[nt][q] = 0.f;

        for (int s = 0; s < NS; s++) {
            CP_WAIT2();
            __syncthreads();
            int slot = s % 3;
            mma_stage32((const uint32_t*)smem + slot*STAGE_S_F, wm, wn, gid, tig, acc);
            __syncthreads();
            if (s + 3 < NS) {
                uint32_t so = slot*STAGE_S_F*4;
                cp16(sa + so, aptr + (s + 3)*32);
                #pragma unroll
                for (int i = 0; i < 4; i++) cp16(sbb[i] + so, bptr[i] + (s + 3)*32);
            }
            CP_COMMIT();
        }

        #pragma unroll
        for (int half = 0; half < 2; half++) {
            int lr = wm*16 + gid + half*8;
            int row = rows_sh[lr];
            if (row < 0) continue;
            float* dst = g_pre + (size_t)row*GDIM + jout*768 + nbase;
            #pragma unroll
            for (int nt = 0; nt < 4; nt++) {
                int n = wn*32 + nt*8 + 2*tig;
                atomicAdd(&dst[n],   acc[nt][half*2 + 0]);
                atomicAdd(&dst[n+1], acc[nt][half*2 + 1]);
            }
        }
    } else {
        // ---- 64x128 path, 3-stage; m-tiles strided on x ----
        int wm = wid & 1, wn = wid >> 1;

        const float* bptr[4];
        uint32_t sbb[4];
        #pragma unroll
        for (int i = 0; i < 4; i++) {
            int idx = i*256 + tid;
            int row = idx >> 3, seg = idx & 7;
            bptr[i] = Wmlp + (size_t)(jout*768 + nbase + row)*KDIM + boff + seg*4;
            sbb[i] = sb + ((64*ROWP) + row*ROWP + seg*4)*4;
        }
        int arow_l[2]; int aseg[2]; uint32_t sa[2];
        #pragma unroll
        for (int i = 0; i < 2; i++) {
            int idx = i*256 + tid;
            arow_l[i] = idx >> 3; aseg[i] = idx & 7;
            sa[i] = sb + (arow_l[i]*ROWP + aseg[i]*4)*4;
        }

        for (int mt0 = blockIdx.x; mt0*64 < cnt; mt0 += gridDim.x) {
            int m0 = mt0*64;
            __syncthreads();
            if (tid < 64) {
                int mi = m0 + tid;
                rows_sh[tid] = (mi < cnt) ? list[mi] : -1;
            }
            __syncthreads();

            const float* aptr[2];
            #pragma unroll
            for (int i = 0; i < 2; i++) {
                int arow = rows_sh[arow_l[i]];
                aptr[i] = abase + (size_t)(arow < 0 ? 0 : arow)*astride + aseg[i]*4;
            }

            #pragma unroll
            for (int s = 0; s < 3; s++) {
                uint32_t so = s*STAGE_F*4;
                #pragma unroll
                for (int i = 0; i < 2; i++) cp16(sa[i] + so, aptr[i] + s*32);
                #pragma unroll
                for (int i = 0; i < 4; i++) cp16(sbb[i] + so, bptr[i] + s*32);
                CP_COMMIT();
            }

            float acc[2][4][4];
            #pragma unroll
            for (int mt = 0; mt < 2; mt++)
                #pragma unroll
                for (int nt = 0; nt < 4; nt++)
                    #pragma unroll
                    for (int q = 0; q < 4; q++) acc[mt][nt][q] = 0.f;

            for (int s = 0; s < NS; s++) {
                CP_WAIT2();
                __syncthreads();
                int slot = s % 3;
                mma_stage64((const uint32_t*)smem + slot*STAGE_F, wm, wn, gid, tig, acc);
                __syncthreads();
                if (s + 3 < NS) {
                    uint32_t so = slot*STAGE_F*4;
                    #pragma unroll
                    for (int i = 0; i < 2; i++) cp16(sa[i] + so, aptr[i] + (s + 3)*32);
                    #pragma unroll
                    for (int i = 0; i < 4; i++) cp16(sbb[i] + so, bptr[i] + (s + 3)*32);
                }
                CP_COMMIT();
            }

            #pragma unroll
            for (int mt = 0; mt < 2; mt++) {
                #pragma unroll
                for (int half = 0; half < 2; half++) {
                    int lr = wm*32 + mt*16 + gid + half*8;
                    int row = rows_sh[lr];
                    if (row < 0) continue;
                    float* dst = g_pre + (size_t)row*GDIM + jout*768 + nbase;
                    #pragma unroll
                    for (int nt = 0; nt < 4; nt++) {
                        int n = wn*32 + nt*8 + 2*tig;
                        atomicAdd(&dst[n],   acc[mt][nt][half*2 + 0]);
                        atomicAdd(&dst[n+1], acc[mt][nt][half*2 + 1]);
                    }
                }
            }
        }
    }
}

// ---------------- fused gate + attention + logits seq-part + state reset ----------------
__global__ __launch_bounds__(256) void k_attn2(const float* __restrict__ seq,
                                               const int* __restrict__ ids,
                                               const float* __restrict__ Wcls,
                                               const float* __restrict__ bcls,
                                               float* __restrict__ out) {
    extern __shared__ float sm[];
    float* sseq = sm;
    float* cbuf = sm + DIM;
    __shared__ float sc[NJ], swt[NJ];
    int m = blockIdx.x, t = threadIdx.x;
    int wid = t >> 5, lane = t & 31;
    unsigned mask = g_amask[m];
    for (int d = t; d < DIM; d += 256) sseq[d] = seq[(size_t)m*DIM + d];
    if (t < NJ) sc[t] = 0.f;
    __syncthreads();

    for (int j = wid; j < NJ; j += 8) {
        if (mask & (1u << j)) {
            const float* pre = g_pre + (size_t)m*GDIM + j*768;
            const float* nf  = g_nflat + (size_t)m*GDIM + j*768;
            float part = 0.f;
            for (int d = lane; d < DIM; d += 32) {
                float cv = (1.f / (1.f + expf(-pre[d]))) * nf[d];
                cbuf[j*768 + d] = cv;
                part += cv * sseq[d];
            }
            #pragma unroll
            for (int o = 16; o; o >>= 1) part += __shfl_xor_sync(0xffffffffu, part, o);
            if (lane == 0) sc[j] = part;
        }
    }
    __syncthreads();
    if (t == 0) {
        float mx = sc[0];
        #pragma unroll
        for (int j = 1; j < NJ; j++) mx = fmaxf(mx, sc[j]);
        float sum = 0.f;
        #pragma unroll
        for (int j = 0; j < NJ; j++) { float e = expf(sc[j]-mx); swt[j] = e; sum += e; }
        float inv = 1.f/sum;
        #pragma unroll
        for (int j = 0; j < NJ; j++) swt[j] *= inv;
    }
    __syncthreads();
    for (int d = t; d < DIM; d += 256) {
        float mix = 0.f;
        unsigned m2 = mask;
        while (m2) {
            int j = __ffs(m2) - 1; m2 &= m2 - 1;
            mix += swt[j] * cbuf[j*768 + d];
        }
        g_combined[(size_t)m*2*DIM + d]       = mix;
        g_combined[(size_t)m*2*DIM + DIM + d] = sseq[d];
    }
    if (wid < NUM_LABELS) {
        const float* wr = Wcls + (size_t)wid*2*DIM;
        float p = 0.f;
        for (int d = lane; d < DIM; d += 32) p += sseq[d]*wr[d];
        #pragma unroll
        for (int o = 16; o; o >>= 1) p += __shfl_xor_sync(0xffffffffu, p, o);
        if (lane == 0) out[m*NUM_LABELS + wid] = p + bcls[wid];
    }
    // state reset for next graph replay (touched entries only)
    if (t == 0) {
        if (m < SLEN) g_lp0[ids[m]] = 0;
        else          g_lp1[ids[m]] = 0;
        g_amask[m] = 0;
    }
}

// ---------------- attn_out GEMM + fused logits tanh-part (64x128, 3-stage, R10 config) ----------------
__global__ __launch_bounds__(256) void k_attnout_mma(const float* __restrict__ Wattn,
                                                     const float* __restrict__ battn,
                                                     const float* __restrict__ Wcls,
                                                     float* __restrict__ out) {
    const int KD = 2*DIM;
    int m0 = blockIdx.x * 64;
    int nbase = blockIdx.y * 128;

    extern __shared__ float smem[];
    __shared__ float sWcls[NUM_LABELS][128];
    uint32_t sb = smem_u32(smem);
    int tid = threadIdx.x;
    int wid = tid >> 5, lane = tid & 31;
    int gid = lane >> 2, tig = lane & 3;
    int wm = wid & 1, wn = wid >> 1;

    for (int idx = tid; idx < NUM_LABELS*128; idx += 256) {
        int l = idx >> 7, c = idx & 127;
        sWcls[l][c] = Wcls[(size_t)l*KD + DIM + nbase + c];
    }

    const float* bptr[4];
    uint32_t sbb[4];
    #pragma unroll
    for (int i = 0; i < 4; i++) {
        int idx = i*256 + tid;
        int row = idx >> 3, seg = idx & 7;
        bptr[i] = Wattn + (size_t)(nbase + row)*KD + seg*4;
        sbb[i] = sb + ((64*ROWP) + row*ROWP + seg*4)*4;
    }
    const float* aptr[2];
    uint32_t sa[2];
    #pragma unroll
    for (int i = 0; i < 2; i++) {
        int idx = i*256 + tid;
        int row = idx >> 3, seg = idx & 7;
        aptr[i] = g_combined + (size_t)(m0 + row)*KD + seg*4;
        sa[i] = sb + (row*ROWP + seg*4)*4;
    }

    const int NS = 48;
    #pragma unroll
    for (int s = 0; s < 3; s++) {
        uint32_t so = s*STAGE_F*4;
        #pragma unroll
        for (int i = 0; i < 2; i++) cp16(sa[i] + so, aptr[i] + s*32);
        #pragma unroll
        for (int i = 0; i < 4; i++) cp16(sbb[i] + so, bptr[i] + s*32);
        CP_COMMIT();
    }

    float acc[2][4][4];
    #pragma unroll
    for (int mt = 0; mt < 2; mt++)
        #pragma unroll
        for (int nt = 0; nt < 4; nt++)
            #pragma unroll
            for (int q = 0; q < 4; q++) acc[mt][nt][q] = 0.f;

    for (int s = 0; s < NS; s++) {
        CP_WAIT2();
        __syncthreads();
        int slot = s % 3;
        mma_stage64((const uint32_t*)smem + slot*STAGE_F, wm, wn, gid, tig, acc);
        __syncthreads();
        if (s + 3 < NS) {
            uint32_t so = slot*STAGE_F*4;
            #pragma unroll
            for (int i = 0; i < 2; i++) cp16(sa[i] + so, aptr[i] + (s + 3)*32);
            #pragma unroll
            for (int i = 0; i < 4; i++) cp16(sbb[i] + so, bptr[i] + (s + 3)*32);
        }
        CP_COMMIT();
    }

    #pragma unroll
    for (int mt = 0; mt < 2; mt++) {
        #pragma unroll
        for (int half = 0; half < 2; half++) {
            int m = m0 + wm*32 + mt*16 + gid + half*8;
            float lg[NUM_LABELS];
            #pragma unroll
            for (int l = 0; l < NUM_LABELS; l++) lg[l] = 0.f;
            #pragma unroll
            for (int nt = 0; nt < 4; nt++) {
                int c = wn*32 + nt*8 + 2*tig;
                int n = nbase + c;
                float v0 = tanhf(acc[mt][nt][half*2 + 0] + battn[n]);
                float v1 = tanhf(acc[mt][nt][half*2 + 1] + battn[n+1]);
                #pragma unroll
                for (int l = 0; l < NUM_LABELS; l++)
                    lg[l] += v0*sWcls[l][c] + v1*sWcls[l][c+1];
            }
            #pragma unroll
            for (int l = 0; l < NUM_LABELS; l++)
                atomicAdd(&out[m*NUM_LABELS + l], lg[l]);
        }
    }
}

// ---------------- launch ----------------
extern "C" void kernel_launch(void* const* d_in, const int* in_sizes, int n_in,
                              void* d_out, int out_size) {
    const float* seq   = (const float*)d_in[0];
    const int*   ids   = (const int*)  d_in[1];
    const int*   nb    = (const int*)  d_in[2];
    const float* Wmlp  = (const float*)d_in[3];
    const float* bmlp  = (const float*)d_in[4];
    const float* Wattn = (const float*)d_in[5];
    const float* battn = (const float*)d_in[6];
    const float* Wcls  = (const float*)d_in[7];
    const float* bcls  = (const float*)d_in[8];
    float* out = (float*)d_out;

    cudaFuncSetAttribute(k_gemmU2,      cudaFuncAttributeMaxDynamicSharedMemorySize, SMEM_U_BYTES);
    cudaFuncSetAttribute(k_attnout_mma, cudaFuncAttributeMaxDynamicSharedMemorySize, SMEM_U_BYTES);

    k_scatter2<<<2, SLEN>>>(ids);
    k_emb_all<<<M_TOK*NJ, 192>>>(nb, seq, bmlp);
    k_pairs2<<<NPAIR, 256>>>();
    dim3 gu(3, 6, NPAIR);
    k_gemmU2<<<gu, 256, SMEM_U_BYTES>>>(seq, Wmlp);
    int attn_smem = (DIM + NJ*DIM)*4;
    k_attn2<<<M_TOK, 256, attn_smem>>>(seq, ids, Wcls, bcls, out);
    dim3 go(M_TOK/64, 6);
    k_attnout_mma<<<go, 256, SMEM_U_BYTES>>>(Wattn, battn, Wcls, out);
}